// round 1
// baseline (speedup 1.0000x reference)
#include <cuda_runtime.h>
#include <cuda_fp16.h>
#include <cstdint>
#include <cstdio>

#define NN   8192
#define IND  512
#define OUTD 256
#define BM   64
#define BK   64
#define LOG2E 1.4426950408889634f

#define SP_STRIDE 72     // halves
#define SH_STRIDE 264    // halves
#define SA_STRIDE 68     // ints
// smem layout (bytes):
//  sP : 0       .. 9216          (64 x 72 halves)
//  sH : 9216    .. 76800         (2 x 64 x 264 halves)
//  sA : 76800   .. 111616        (2 x 64 x 68 ints)
//  sEr: 111616  .. 112128        (2 x 64 floats)
//  sEl: 112128  .. 112384        (64 floats)
//  sL : 112384  .. 112640        (64 floats)
#define SMEM_FUSED 112640

// ---------------- scratch (no mallocs allowed) ----------------
__device__ __half g_h16[(size_t)NN * OUTD];
__device__ float  g_el[NN];
__device__ float  g_er[NN];
__device__ float  g_ul[IND];
__device__ float  g_ur[IND];
__device__ float  g_cb[2];

// ---------------- small helpers ----------------
__device__ __forceinline__ uint32_t smem_u32(const void* p) {
    return (uint32_t)__cvta_generic_to_shared(p);
}
__device__ __forceinline__ void cp16(void* dst, const void* src) {
    asm volatile("cp.async.cg.shared.global [%0], [%1], 16;" ::
                 "r"(smem_u32(dst)), "l"(src));
}
__device__ __forceinline__ void cp_commit() { asm volatile("cp.async.commit_group;"); }
__device__ __forceinline__ void cp_wait0()  { asm volatile("cp.async.wait_group 0;"); }

__device__ __forceinline__ void ldmA(uint32_t* r, const void* p) {
    uint32_t a = smem_u32(p);
    asm volatile("ldmatrix.sync.aligned.m8n8.x4.shared.b16 {%0,%1,%2,%3}, [%4];"
                 : "=r"(r[0]), "=r"(r[1]), "=r"(r[2]), "=r"(r[3]) : "r"(a));
}
__device__ __forceinline__ void ldmBT(uint32_t* r, const void* p) {
    uint32_t a = smem_u32(p);
    asm volatile("ldmatrix.sync.aligned.m8n8.x4.trans.shared.b16 {%0,%1,%2,%3}, [%4];"
                 : "=r"(r[0]), "=r"(r[1]), "=r"(r[2]), "=r"(r[3]) : "r"(a));
}
__device__ __forceinline__ void mma16816(float* c, const uint32_t* a,
                                         uint32_t b0, uint32_t b1) {
    asm volatile(
        "mma.sync.aligned.m16n8k16.row.col.f32.f16.f16.f32 "
        "{%0,%1,%2,%3},{%4,%5,%6,%7},{%8,%9},{%0,%1,%2,%3};"
        : "+f"(c[0]), "+f"(c[1]), "+f"(c[2]), "+f"(c[3])
        : "r"(a[0]), "r"(a[1]), "r"(a[2]), "r"(a[3]), "r"(b0), "r"(b1));
}
__device__ __forceinline__ float ex2f(float x) {
    float y; asm("ex2.approx.ftz.f32 %0, %1;" : "=f"(y) : "f"(x)); return y;
}

// ---------------- kernel 1: u_l = W @ a_l, u_r = W @ a_r, consts ----------------
__global__ void __launch_bounds__(256) u_kernel(const float* __restrict__ W,
                                                const float* __restrict__ b,
                                                const float* __restrict__ a,
                                                const float* __restrict__ ab) {
    __shared__ float sa[2 * OUTD];
    const int tid = threadIdx.x;
    sa[tid]       = a[tid];
    sa[tid + 256] = a[tid + 256];
    __syncthreads();
    for (int k = tid; k < IND; k += 256) {
        float ul = 0.f, ur = 0.f;
        const float* wr = W + (size_t)k * OUTD;
        #pragma unroll 4
        for (int n = 0; n < OUTD; ++n) {
            float w = wr[n];
            ul += w * sa[n];
            ur += w * sa[OUTD + n];
        }
        g_ul[k] = ul;
        g_ur[k] = ur;
    }
    if (tid == 0) {
        float bl = 0.f, br = 0.f;
        for (int n = 0; n < OUTD; ++n) {
            bl += b[n] * sa[n];
            br += b[n] * sa[OUTD + n];
        }
        g_cb[0] = bl + ab[0];   // fold a_bias once into el
        g_cb[1] = br;
    }
}

// ---------------- kernel 2: el[i] = X_i . u_l + c0 ; er[i] = X_i . u_r + c1 ----
__global__ void __launch_bounds__(256) eler_kernel(const float* __restrict__ X) {
    __shared__ float sul[IND], sur[IND];
    const int tid = threadIdx.x;
    sul[tid]       = g_ul[tid];
    sul[tid + 256] = g_ul[tid + 256];
    sur[tid]       = g_ur[tid];
    sur[tid + 256] = g_ur[tid + 256];
    __syncthreads();
    const int lane = tid & 31;
    const int w    = tid >> 5;
    const int i    = blockIdx.x * 8 + w;
    const float* xr = X + (size_t)i * IND;
    float dl = 0.f, dr = 0.f;
    #pragma unroll
    for (int q = 0; q < 4; ++q) {
        int c = q * 128 + lane * 4;
        float4 v = *(const float4*)(xr + c);
        dl += v.x * sul[c] + v.y * sul[c + 1] + v.z * sul[c + 2] + v.w * sul[c + 3];
        dr += v.x * sur[c] + v.y * sur[c + 1] + v.z * sur[c + 2] + v.w * sur[c + 3];
    }
    #pragma unroll
    for (int o = 16; o > 0; o >>= 1) {
        dl += __shfl_xor_sync(0xffffffffu, dl, o);
        dr += __shfl_xor_sync(0xffffffffu, dr, o);
    }
    if (lane == 0) {
        g_el[i] = dl + g_cb[0];
        g_er[i] = dr + g_cb[1];
    }
}

// ---------------- kernel 3: h16 = fp16(X @ W + b) ----------------
__global__ void __launch_bounds__(256) gemm1_kernel(const float* __restrict__ X,
                                                    const float* __restrict__ W,
                                                    const float* __restrict__ b) {
    __shared__ __half sX[128 * 72];
    __shared__ __half sW[64 * 136];
    const int tid  = threadIdx.x;
    const int lane = tid & 31;
    const int wid  = tid >> 5;
    const int mblk = blockIdx.x * 128;
    const int nblk = blockIdx.y * 128;
    const int wm   = (wid >> 1) * 32;
    const int wn   = (wid & 1) * 64;

    float acc[2][8][4];
    #pragma unroll
    for (int i = 0; i < 2; ++i)
        #pragma unroll
        for (int j = 0; j < 8; ++j)
            #pragma unroll
            for (int k = 0; k < 4; ++k) acc[i][j][k] = 0.f;

    for (int k0 = 0; k0 < IND; k0 += 64) {
        __syncthreads();
        #pragma unroll
        for (int pass = 0; pass < 8; ++pass) {
            int row = pass * 16 + (tid >> 4);
            int col = (tid & 15) * 4;
            float4 v = *(const float4*)(X + (size_t)(mblk + row) * IND + k0 + col);
            *(__half2*)&sX[row * 72 + col]     = __floats2half2_rn(v.x, v.y);
            *(__half2*)&sX[row * 72 + col + 2] = __floats2half2_rn(v.z, v.w);
        }
        #pragma unroll
        for (int pass = 0; pass < 8; ++pass) {
            int row = pass * 8 + (tid >> 5);
            int col = (tid & 31) * 4;
            float4 v = *(const float4*)(W + (size_t)(k0 + row) * OUTD + nblk + col);
            *(__half2*)&sW[row * 136 + col]     = __floats2half2_rn(v.x, v.y);
            *(__half2*)&sW[row * 136 + col + 2] = __floats2half2_rn(v.z, v.w);
        }
        __syncthreads();
        #pragma unroll
        for (int kk = 0; kk < 4; ++kk) {
            int kb = kk * 16;
            uint32_t A[2][4];
            #pragma unroll
            for (int mf = 0; mf < 2; ++mf)
                ldmA(A[mf], &sX[(wm + mf * 16 + (lane & 15)) * 72 + kb + (lane >> 4) * 8]);
            #pragma unroll
            for (int nf = 0; nf < 4; ++nf) {
                uint32_t B[4];
                ldmBT(B, &sW[(kb + (lane & 15)) * 136 + wn + nf * 16 + (lane >> 4) * 8]);
                #pragma unroll
                for (int mf = 0; mf < 2; ++mf) {
                    mma16816(acc[mf][2 * nf],     A[mf], B[0], B[1]);
                    mma16816(acc[mf][2 * nf + 1], A[mf], B[2], B[3]);
                }
            }
        }
    }
    #pragma unroll
    for (int mf = 0; mf < 2; ++mf) {
        int grow = mblk + wm + mf * 16 + (lane >> 2);
        #pragma unroll
        for (int nf = 0; nf < 8; ++nf) {
            int gcol = nblk + wn + nf * 8 + (lane & 3) * 2;
            float b0 = b[gcol], b1 = b[gcol + 1];
            *(__half2*)&g_h16[(size_t)grow * OUTD + gcol] =
                __floats2half2_rn(acc[mf][nf][0] + b0, acc[mf][nf][1] + b1);
            *(__half2*)&g_h16[(size_t)(grow + 8) * OUTD + gcol] =
                __floats2half2_rn(acc[mf][nf][2] + b0, acc[mf][nf][3] + b1);
        }
    }
}

// ---------------- kernel 4: fused masked-softmax attention + aggregation -------
// out[i,:] = sum_j adj ? exp(lrelu(el_i+er_j))*2^-6 * h_j : 0   /  rowsum
__global__ void __launch_bounds__(256) gat_fused_kernel(const int* __restrict__ adj,
                                                        float* __restrict__ out) {
    extern __shared__ char smem[];
    __half* sP  = (__half*)smem;
    __half* sH  = (__half*)(smem + 9216);
    int*    sA  = (int*)(smem + 76800);
    float*  sEr = (float*)(smem + 111616);
    float*  sEl = (float*)(smem + 112128);
    float*  sL  = (float*)(smem + 112384);

    const int tid  = threadIdx.x;
    const int lane = tid & 31;
    const int wid  = tid >> 5;
    const int i0   = blockIdx.x * BM;
    const int r    = tid >> 2;          // 0..63 (row in tile)
    const int cg   = (tid & 3) << 4;    // 0,16,32,48 (col group)

    if (tid < BM) sEl[tid] = g_el[i0 + tid];

    // prologue: stage tile 0
    {
        #pragma unroll
        for (int pass = 0; pass < 8; ++pass) {
            int row = pass * 8 + wid;
            cp16(&sH[row * SH_STRIDE + lane * 8],
                 &g_h16[(size_t)row * OUTD + lane * 8]);
        }
        #pragma unroll
        for (int q = 0; q < 4; ++q)
            cp16(&sA[r * SA_STRIDE + cg + 4 * q],
                 adj + (size_t)(i0 + r) * NN + cg + 4 * q);
        if (tid < 16) cp16(&sEr[tid * 4], g_er + tid * 4);
        cp_commit();
    }

    float acc[2][8][4];
    #pragma unroll
    for (int i = 0; i < 2; ++i)
        #pragma unroll
        for (int j = 0; j < 8; ++j)
            #pragma unroll
            for (int k = 0; k < 4; ++k) acc[i][j][k] = 0.f;
    float psum = 0.f;

    const int wm = (wid >> 2) * 32;
    const int wn = (wid & 3) * 64;

    for (int t = 0; t < NN / BK; ++t) {
        const int buf = t & 1;
        cp_wait0();
        __syncthreads();

        if (t + 1 < NN / BK) {
            const int nb = buf ^ 1;
            const int jb = (t + 1) * BK;
            #pragma unroll
            for (int pass = 0; pass < 8; ++pass) {
                int row = pass * 8 + wid;
                cp16(&sH[nb * BK * SH_STRIDE + row * SH_STRIDE + lane * 8],
                     &g_h16[(size_t)(jb + row) * OUTD + lane * 8]);
            }
            #pragma unroll
            for (int q = 0; q < 4; ++q)
                cp16(&sA[nb * BM * SA_STRIDE + r * SA_STRIDE + cg + 4 * q],
                     adj + (size_t)(i0 + r) * NN + jb + cg + 4 * q);
            if (tid < 16) cp16(&sEr[nb * BK + tid * 4], g_er + jb + tid * 4);
            cp_commit();
        }

        // P tile: exp(lrelu(el+er)) * 2^-6, masked, fp16
        {
            const float elv = sEl[r];
            const int* sAb  = sA + buf * BM * SA_STRIDE + r * SA_STRIDE;
            const float* serb = sEr + buf * BK;
            #pragma unroll
            for (int q = 0; q < 4; ++q) {
                int4 av = *(const int4*)(sAb + cg + 4 * q);
                int vv[4] = {av.x, av.y, av.z, av.w};
                __half ph[4];
                #pragma unroll
                for (int e = 0; e < 4; ++e) {
                    int c = cg + 4 * q + e;
                    float tt  = elv + serb[c];
                    float arg = fmaxf(tt, 0.2f * tt) * LOG2E - 6.0f;
                    float p   = (vv[e] > 0) ? ex2f(arg) : 0.f;
                    ph[e] = __float2half_rn(p);
                    psum += __half2float(ph[e]);   // consistent with numerator
                }
                *(__half2*)&sP[r * SP_STRIDE + cg + 4 * q]     = __halves2half2(ph[0], ph[1]);
                *(__half2*)&sP[r * SP_STRIDE + cg + 4 * q + 2] = __halves2half2(ph[2], ph[3]);
            }
        }
        __syncthreads();

        // MMA: acc += P(64x64) @ H(64x256)
        const __half* sHb = sH + buf * BK * SH_STRIDE;
        #pragma unroll
        for (int kk = 0; kk < 4; ++kk) {
            const int kb = kk * 16;
            uint32_t A[2][4];
            #pragma unroll
            for (int mf = 0; mf < 2; ++mf)
                ldmA(A[mf], &sP[(wm + mf * 16 + (lane & 15)) * SP_STRIDE + kb + (lane >> 4) * 8]);
            #pragma unroll
            for (int nf = 0; nf < 4; ++nf) {
                uint32_t B[4];
                ldmBT(B, &sHb[(kb + (lane & 15)) * SH_STRIDE + wn + nf * 16 + (lane >> 4) * 8]);
                #pragma unroll
                for (int mf = 0; mf < 2; ++mf) {
                    mma16816(acc[mf][2 * nf],     A[mf], B[0], B[1]);
                    mma16816(acc[mf][2 * nf + 1], A[mf], B[2], B[3]);
                }
            }
        }
    }

    // rowsum reduce (4 threads per row are consecutive lanes)
    psum += __shfl_xor_sync(0xffffffffu, psum, 1);
    psum += __shfl_xor_sync(0xffffffffu, psum, 2);
    if ((tid & 3) == 0) sL[r] = psum;
    __syncthreads();

    #pragma unroll
    for (int mf = 0; mf < 2; ++mf) {
        int row0   = wm + mf * 16 + (lane >> 2);
        float inv0 = 1.0f / sL[row0];
        float inv1 = 1.0f / sL[row0 + 8];
        #pragma unroll
        for (int nf = 0; nf < 8; ++nf) {
            int col = wn + nf * 8 + (lane & 3) * 2;
            float2 v0 = make_float2(acc[mf][nf][0] * inv0, acc[mf][nf][1] * inv0);
            float2 v1 = make_float2(acc[mf][nf][2] * inv1, acc[mf][nf][3] * inv1);
            *(float2*)&out[(size_t)(i0 + row0) * OUTD + col]     = v0;
            *(float2*)&out[(size_t)(i0 + row0 + 8) * OUTD + col] = v1;
        }
    }
}

// ---------------- launch ----------------
extern "C" void kernel_launch(void* const* d_in, const int* in_sizes, int n_in,
                              void* d_out, int out_size) {
    const int*   adj = (const int*)d_in[0];
    const float* X   = (const float*)d_in[1];
    const float* W   = (const float*)d_in[2];
    const float* b   = (const float*)d_in[3];
    const float* a   = (const float*)d_in[4];
    const float* ab  = (const float*)d_in[5];
    float* out = (float*)d_out;

    cudaFuncSetAttribute(gat_fused_kernel,
                         cudaFuncAttributeMaxDynamicSharedMemorySize, SMEM_FUSED);

    u_kernel<<<1, 256>>>(W, b, a, ab);
    eler_kernel<<<NN / 8, 256>>>(X);
    gemm1_kernel<<<dim3(NN / 128, OUTD / 128), 256>>>(X, W, b);
    gat_fused_kernel<<<NN / BM, 256, SMEM_FUSED>>>(adj, out);
}

// round 4
// speedup vs baseline: 1.3409x; 1.3409x over previous
#include <cuda_runtime.h>
#include <cuda_fp16.h>
#include <cstdint>

#define NN    8192
#define IND   512
#define OUTD  256
#define BM    64
#define BK    64
#define SPLITS 2
#define JRANGE (NN / SPLITS)      // 4096
#define NTILES (JRANGE / BK)      // 64
#define LOG2E 1.4426950408889634f
#define THRESH 0.015625f          // 2^-6: e1*f1 > 2^-6  <=>  el+er > 0

// ---- dynamic smem layout for fused kernel (bytes) ----
#define SP_OFF   0                 // 2 x (64 x 72 half)   = 18432
#define SH_OFF   18432             // 2 x (64 x 264 half)  = 67584
#define SER_OFF  86016             // 2 x 64 float2        = 1024
#define SEL_OFF  87040             // 64 float2            = 512
#define SMEM_FUSED 87552
#define SP_STRIDE 72               // halves
#define SH_STRIDE 264              // halves
#define SP_BUF 9216                // bytes per sP buffer
#define SH_BUF 33792               // bytes per sH buffer

// ---------------- scratch ----------------
__device__ __half g_h16[(size_t)NN * OUTD];              // h fp16, row-major [8192][256]
__device__ float  g_part[(size_t)SPLITS * NN * OUTD];    // split-K partial numerators
__device__ float  g_Lp[SPLITS * NN];                     // split-K partial rowsums
__device__ float2 g_elx[NN];
__device__ float2 g_erx[NN];
__device__ float  g_ul[IND];
__device__ float  g_ur[IND];
__device__ float  g_cb[2];

// ---------------- helpers ----------------
__device__ __forceinline__ uint32_t smem_u32(const void* p) {
    return (uint32_t)__cvta_generic_to_shared(p);
}
__device__ __forceinline__ void cp16(void* dst, const void* src) {
    asm volatile("cp.async.cg.shared.global [%0], [%1], 16;" ::
                 "r"(smem_u32(dst)), "l"(src) : "memory");
}
__device__ __forceinline__ void cp_commit() {
    asm volatile("cp.async.commit_group;" ::: "memory");
}
__device__ __forceinline__ void cp_wait0() {
    asm volatile("cp.async.wait_group 0;" ::: "memory");
}
__device__ __forceinline__ float ex2f(float x) {
    float y; asm("ex2.approx.ftz.f32 %0, %1;" : "=f"(y) : "f"(x)); return y;
}
__device__ __forceinline__ uint32_t pack2h(__half a, __half b) {
    return (uint32_t)__half_as_ushort(a) | ((uint32_t)__half_as_ushort(b) << 16);
}
__device__ __forceinline__ void ldmA(uint32_t* r, const void* p) {
    uint32_t a = smem_u32(p);
    asm volatile("ldmatrix.sync.aligned.m8n8.x4.shared.b16 {%0,%1,%2,%3}, [%4];"
                 : "=r"(r[0]), "=r"(r[1]), "=r"(r[2]), "=r"(r[3]) : "r"(a));
}
__device__ __forceinline__ void ldmBT(uint32_t* r, const void* p) {
    uint32_t a = smem_u32(p);
    asm volatile("ldmatrix.sync.aligned.m8n8.x4.trans.shared.b16 {%0,%1,%2,%3}, [%4];"
                 : "=r"(r[0]), "=r"(r[1]), "=r"(r[2]), "=r"(r[3]) : "r"(a));
}
__device__ __forceinline__ void mma16816(float* c, const uint32_t* a,
                                         uint32_t b0, uint32_t b1) {
    asm volatile(
        "mma.sync.aligned.m16n8k16.row.col.f32.f16.f16.f32 "
        "{%0,%1,%2,%3},{%4,%5,%6,%7},{%8,%9},{%0,%1,%2,%3};"
        : "+f"(c[0]), "+f"(c[1]), "+f"(c[2]), "+f"(c[3])
        : "r"(a[0]), "r"(a[1]), "r"(a[2]), "r"(a[3]), "r"(b0), "r"(b1));
}

// ---------------- kernel 1: u_l = W @ a_l, u_r = W @ a_r ----------------
__global__ void __launch_bounds__(256) u_kernel(const float* __restrict__ W,
                                                const float* __restrict__ b,
                                                const float* __restrict__ a,
                                                const float* __restrict__ ab) {
    __shared__ float sa[2 * OUTD];
    const int tid = threadIdx.x;
    sa[tid]       = a[tid];
    sa[tid + 256] = a[tid + 256];
    __syncthreads();
    const int lane = tid & 31;
    const int k    = blockIdx.x * 8 + (tid >> 5);   // 0..511
    const float* wr = W + (size_t)k * OUTD + lane * 8;
    float4 v0 = *(const float4*)(wr);
    float4 v1 = *(const float4*)(wr + 4);
    const float* s0 = sa + lane * 8;
    const float* s1 = sa + OUTD + lane * 8;
    float ul = v0.x * s0[0] + v0.y * s0[1] + v0.z * s0[2] + v0.w * s0[3]
             + v1.x * s0[4] + v1.y * s0[5] + v1.z * s0[6] + v1.w * s0[7];
    float ur = v0.x * s1[0] + v0.y * s1[1] + v0.z * s1[2] + v0.w * s1[3]
             + v1.x * s1[4] + v1.y * s1[5] + v1.z * s1[6] + v1.w * s1[7];
    #pragma unroll
    for (int o = 16; o > 0; o >>= 1) {
        ul += __shfl_xor_sync(0xffffffffu, ul, o);
        ur += __shfl_xor_sync(0xffffffffu, ur, o);
    }
    if (lane == 0) { g_ul[k] = ul; g_ur[k] = ur; }
    if (blockIdx.x == 0 && tid == 0) {
        float bl = 0.f, br = 0.f;
        for (int n = 0; n < OUTD; ++n) {
            bl += b[n] * sa[n];
            br += b[n] * sa[OUTD + n];
        }
        g_cb[0] = bl + ab[0];   // a_bias folded into el
        g_cb[1] = br;
    }
}

// ---------------- kernel 2: per-node factorized exps of el/er ----------------
__global__ void __launch_bounds__(256) eler_kernel(const float* __restrict__ X) {
    __shared__ float sul[IND], sur[IND];
    const int tid = threadIdx.x;
    sul[tid]       = g_ul[tid];
    sul[tid + 256] = g_ul[tid + 256];
    sur[tid]       = g_ur[tid];
    sur[tid + 256] = g_ur[tid + 256];
    __syncthreads();
    const int lane = tid & 31;
    const int w    = tid >> 5;
    const int i    = blockIdx.x * 8 + w;
    const float* xr = X + (size_t)i * IND;
    float dl = 0.f, dr = 0.f;
    #pragma unroll
    for (int q = 0; q < 4; ++q) {
        int c = q * 128 + lane * 4;
        float4 v = *(const float4*)(xr + c);
        dl += v.x * sul[c] + v.y * sul[c + 1] + v.z * sul[c + 2] + v.w * sul[c + 3];
        dr += v.x * sur[c] + v.y * sur[c + 1] + v.z * sur[c + 2] + v.w * sur[c + 3];
    }
    #pragma unroll
    for (int o = 16; o > 0; o >>= 1) {
        dl += __shfl_xor_sync(0xffffffffu, dl, o);
        dr += __shfl_xor_sync(0xffffffffu, dr, o);
    }
    if (lane == 0) {
        float el = dl + g_cb[0];
        float er = dr + g_cb[1];
        float2 ev, fv;
        ev.x = ex2f(el * LOG2E - 3.0f);
        ev.y = ex2f(el * (0.2f * LOG2E) - 3.0f);
        fv.x = ex2f(er * LOG2E - 3.0f);
        fv.y = ex2f(er * (0.2f * LOG2E) - 3.0f);
        g_elx[i] = ev;
        g_erx[i] = fv;
    }
}

// ---------------- kernel 3: h16 = fp16(X @ W + b), row-major ----------------
__global__ void __launch_bounds__(256) gemm1_kernel(const float* __restrict__ X,
                                                    const float* __restrict__ W,
                                                    const float* __restrict__ b) {
    __shared__ __half sX[128 * 72];
    __shared__ __half sW[64 * 136];
    const int tid  = threadIdx.x;
    const int lane = tid & 31;
    const int wid  = tid >> 5;
    const int mblk = blockIdx.x * 128;
    const int nblk = blockIdx.y * 128;
    const int wm   = (wid >> 1) * 32;
    const int wn   = (wid & 1) * 64;

    float acc[2][8][4];
    #pragma unroll
    for (int i = 0; i < 2; ++i)
        #pragma unroll
        for (int j = 0; j < 8; ++j)
            #pragma unroll
            for (int k = 0; k < 4; ++k) acc[i][j][k] = 0.f;

    for (int k0 = 0; k0 < IND; k0 += 64) {
        __syncthreads();
        #pragma unroll
        for (int pass = 0; pass < 8; ++pass) {
            int row = pass * 16 + (tid >> 4);
            int col = (tid & 15) * 4;
            float4 v = *(const float4*)(X + (size_t)(mblk + row) * IND + k0 + col);
            *(__half2*)&sX[row * 72 + col]     = __floats2half2_rn(v.x, v.y);
            *(__half2*)&sX[row * 72 + col + 2] = __floats2half2_rn(v.z, v.w);
        }
        #pragma unroll
        for (int pass = 0; pass < 8; ++pass) {
            int row = pass * 8 + (tid >> 5);
            int col = (tid & 31) * 4;
            float4 v = *(const float4*)(W + (size_t)(k0 + row) * OUTD + nblk + col);
            *(__half2*)&sW[row * 136 + col]     = __floats2half2_rn(v.x, v.y);
            *(__half2*)&sW[row * 136 + col + 2] = __floats2half2_rn(v.z, v.w);
        }
        __syncthreads();
        #pragma unroll
        for (int kk = 0; kk < 4; ++kk) {
            int kb = kk * 16;
            uint32_t A[2][4];
            #pragma unroll
            for (int mf = 0; mf < 2; ++mf)
                ldmA(A[mf], &sX[(wm + mf * 16 + (lane & 15)) * 72 + kb + (lane >> 4) * 8]);
            #pragma unroll
            for (int nf = 0; nf < 4; ++nf) {
                uint32_t B[4];
                ldmBT(B, &sW[(kb + (lane & 15)) * 136 + wn + nf * 16 + (lane >> 4) * 8]);
                #pragma unroll
                for (int mf = 0; mf < 2; ++mf) {
                    mma16816(acc[mf][2 * nf],     A[mf], B[0], B[1]);
                    mma16816(acc[mf][2 * nf + 1], A[mf], B[2], B[3]);
                }
            }
        }
    }
    #pragma unroll
    for (int mf = 0; mf < 2; ++mf) {
        int grow = mblk + wm + mf * 16 + (lane >> 2);
        #pragma unroll
        for (int nf = 0; nf < 8; ++nf) {
            int gcol = nblk + wn + nf * 8 + (lane & 3) * 2;
            float b0 = b[gcol], b1 = b[gcol + 1];
            *(__half2*)&g_h16[(size_t)grow * OUTD + gcol] =
                __floats2half2_rn(acc[mf][nf][0] + b0, acc[mf][nf][1] + b1);
            *(__half2*)&g_h16[(size_t)(grow + 8) * OUTD + gcol] =
                __floats2half2_rn(acc[mf][nf][2] + b0, acc[mf][nf][3] + b1);
        }
    }
}

// ---------------- kernel 4: fused masked-softmax attention (mma.sync, 2 CTAs/SM) --
__global__ void __launch_bounds__(256, 2) gat_fused_kernel(const int* __restrict__ adj) {
    extern __shared__ __align__(256) char smem[];
    __half* sP  = (__half*)(smem + SP_OFF);
    float2* sEl = (float2*)(smem + SEL_OFF);

    const int tid  = threadIdx.x;
    const int lane = tid & 31;
    const int wid  = tid >> 5;
    const int s    = blockIdx.x & 1;
    const int rb   = blockIdx.x >> 1;
    const int i0   = rb * BM;
    const int J0   = s * JRANGE;

    const int r  = tid >> 2;           // 0..63
    const int cg = (tid & 3) << 4;     // 0,16,32,48
    const int* arow = adj + (size_t)(i0 + r) * NN + J0 + cg;

    if (tid < BM) sEl[tid] = g_elx[i0 + tid];

    // prologue: stage tile 0
    #pragma unroll
    for (int p = 0; p < 8; ++p) {
        int idx = p * 256 + tid;
        int row = idx >> 5, c = idx & 31;
        cp16(smem + SH_OFF + row * (SH_STRIDE * 2) + c * 16,
             g_h16 + (size_t)(J0 + row) * OUTD + c * 8);
    }
    if (tid < 32) cp16(smem + SER_OFF + tid * 16, g_erx + J0 + tid * 2);
    cp_commit();

    int4 a_cur[4];
    #pragma unroll
    for (int q = 0; q < 4; ++q) a_cur[q] = *(const int4*)(arow + 4 * q);

    float acc[2][8][4];
    #pragma unroll
    for (int i = 0; i < 2; ++i)
        #pragma unroll
        for (int j = 0; j < 8; ++j)
            #pragma unroll
            for (int k = 0; k < 4; ++k) acc[i][j][k] = 0.f;
    float psum = 0.f;

    const int wm = (wid >> 2) * 32;
    const int wn = (wid & 3) * 64;

    for (int t = 0; t < NTILES; ++t) {
        const int b2 = t & 1;

        cp_wait0();
        __syncthreads();   // sH[b2]/sEr[b2] ready; all warps past MMA(t-1)

        if (t + 1 < NTILES) {
            const int jb = J0 + (t + 1) * BK;
            #pragma unroll
            for (int p = 0; p < 8; ++p) {
                int idx = p * 256 + tid;
                int row = idx >> 5, c = idx & 31;
                cp16(smem + SH_OFF + (b2 ^ 1) * SH_BUF + row * (SH_STRIDE * 2) + c * 16,
                     g_h16 + (size_t)(jb + row) * OUTD + c * 8);
            }
            if (tid < 32) cp16(smem + SER_OFF + (b2 ^ 1) * 512 + tid * 16, g_erx + jb + tid * 2);
            cp_commit();
        }

        // P tile (64x64): p = adj ? (e1*f1 > 2^-6 ? e1*f1 : e2*f2) : 0
        {
            const float2 ev = sEl[r];
            const float2* fv = (const float2*)(smem + SER_OFF + b2 * 512);
            char* pdst = (char*)sP + b2 * SP_BUF + r * (SP_STRIDE * 2) + cg * 2;
            uint32_t pk[8];
            #pragma unroll
            for (int q = 0; q < 4; ++q) {
                const int4 av = a_cur[q];
                const int mv[4] = {av.x, av.y, av.z, av.w};
                __half ph[4];
                #pragma unroll
                for (int e = 0; e < 4; ++e) {
                    float2 f = fv[cg + 4 * q + e];
                    float p1 = ev.x * f.x;
                    float p2 = ev.y * f.y;
                    float p  = (p1 > THRESH) ? p1 : p2;
                    p = (mv[e] > 0) ? p : 0.f;
                    psum += p;
                    ph[e] = __float2half_rn(p);
                }
                pk[2 * q]     = pack2h(ph[0], ph[1]);
                pk[2 * q + 1] = pack2h(ph[2], ph[3]);
            }
            *(uint4*)(pdst)      = make_uint4(pk[0], pk[1], pk[2], pk[3]);
            *(uint4*)(pdst + 16) = make_uint4(pk[4], pk[5], pk[6], pk[7]);
        }

        // prefetch adj tile t+1 (completes during MMA below)
        if (t + 1 < NTILES) {
            const int* an = arow + (t + 1) * BK;
            #pragma unroll
            for (int q = 0; q < 4; ++q) a_cur[q] = *(const int4*)(an + 4 * q);
        }

        __syncthreads();   // sP[b2] fully written

        const __half* sPb = (const __half*)((char*)sP + b2 * SP_BUF);
        const __half* sHb = (const __half*)(smem + SH_OFF + b2 * SH_BUF);
        #pragma unroll
        for (int kk = 0; kk < 4; ++kk) {
            const int kb = kk * 16;
            uint32_t A[2][4];
            #pragma unroll
            for (int mf = 0; mf < 2; ++mf)
                ldmA(A[mf], &sPb[(wm + mf * 16 + (lane & 15)) * SP_STRIDE + kb + (lane >> 4) * 8]);
            #pragma unroll
            for (int nf = 0; nf < 4; ++nf) {
                uint32_t B[4];
                ldmBT(B, &sHb[(kb + (lane & 15)) * SH_STRIDE + wn + nf * 16 + (lane >> 4) * 8]);
                #pragma unroll
                for (int mf = 0; mf < 2; ++mf) {
                    mma16816(acc[mf][2 * nf],     A[mf], B[0], B[1]);
                    mma16816(acc[mf][2 * nf + 1], A[mf], B[2], B[3]);
                }
            }
        }
    }

    psum += __shfl_xor_sync(0xffffffffu, psum, 1);
    psum += __shfl_xor_sync(0xffffffffu, psum, 2);
    if ((tid & 3) == 0) g_Lp[s * NN + i0 + r] = psum;

    #pragma unroll
    for (int mf = 0; mf < 2; ++mf) {
        int row0 = wm + mf * 16 + (lane >> 2);
        float* d0 = g_part + ((size_t)s * NN + i0 + row0) * OUTD;
        float* d1 = g_part + ((size_t)s * NN + i0 + row0 + 8) * OUTD;
        #pragma unroll
        for (int nf = 0; nf < 8; ++nf) {
            int col = wn + nf * 8 + (lane & 3) * 2;
            *(float2*)(d0 + col) = make_float2(acc[mf][nf][0], acc[mf][nf][1]);
            *(float2*)(d1 + col) = make_float2(acc[mf][nf][2], acc[mf][nf][3]);
        }
    }
}

// ---------------- kernel 5: combine split-K partials ----------------
__global__ void __launch_bounds__(256) combine_kernel(float* __restrict__ out) {
    const int gid = blockIdx.x * 256 + threadIdx.x;
    const int row = gid >> 6;
    const int c   = (gid & 63) * 4;
    const float4 x0 = *(const float4*)(g_part + (size_t)row * OUTD + c);
    const float4 x1 = *(const float4*)(g_part + (size_t)NN * OUTD + (size_t)row * OUTD + c);
    const float inv = 1.0f / (g_Lp[row] + g_Lp[NN + row]);
    float4 o;
    o.x = (x0.x + x1.x) * inv;
    o.y = (x0.y + x1.y) * inv;
    o.z = (x0.z + x1.z) * inv;
    o.w = (x0.w + x1.w) * inv;
    *(float4*)(out + (size_t)row * OUTD + c) = o;
}

// ---------------- launch ----------------
extern "C" void kernel_launch(void* const* d_in, const int* in_sizes, int n_in,
                              void* d_out, int out_size) {
    const int*   adj = (const int*)d_in[0];
    const float* X   = (const float*)d_in[1];
    const float* W   = (const float*)d_in[2];
    const float* b   = (const float*)d_in[3];
    const float* a   = (const float*)d_in[4];
    const float* ab  = (const float*)d_in[5];
    float* out = (float*)d_out;

    cudaFuncSetAttribute(gat_fused_kernel,
                         cudaFuncAttributeMaxDynamicSharedMemorySize, SMEM_FUSED);

    u_kernel<<<64, 256>>>(W, b, a, ab);
    eler_kernel<<<NN / 8, 256>>>(X);
    gemm1_kernel<<<dim3(NN / 128, OUTD / 128), 256>>>(X, W, b);
    gat_fused_kernel<<<(NN / BM) * SPLITS, 256, SMEM_FUSED>>>(adj);
    combine_kernel<<<(NN * OUTD / 4) / 256, 256>>>(out);
}

// round 5
// speedup vs baseline: 1.4385x; 1.0728x over previous
#include <cuda_runtime.h>
#include <cuda_fp16.h>
#include <cstdint>

#define NN    8192
#define IND   512
#define OUTD  256
#define BM    64
#define BK    64
#define SPLITS 2
#define JRANGE (NN / SPLITS)      // 4096
#define NTILES (JRANGE / BK)      // 64
#define LOG2E 1.4426950408889634f
#define THRESH 0.015625f          // 2^-6: e1*f1 > 2^-6  <=>  el+er > 0

// ---- dynamic smem layout for fused kernel (bytes) ----
// sP: 2 x (64 rows x 128B, swizzled)  = 16384 @ 0
// sH: 3 x (64 rows x 512B, swizzled)  = 98304 @ 16384
#define SP_OFF   0
#define SP_BUF   8192
#define SH_OFF   16384
#define SH_BUF   32768
#define SMEM_FUSED 114688          // fits 2 CTAs/SM (229376 <= 233472)

// XOR swizzle: 16B chunk cb within a row, rotated by row&7
#define SWZ(row, cb) ((((cb) ^ ((row) & 7))) * 16)

// ---------------- scratch ----------------
__device__ __half g_h16[(size_t)NN * OUTD];              // h fp16, row-major [8192][256]
__device__ float  g_part[(size_t)SPLITS * NN * OUTD];    // split-K partial numerators
__device__ float  g_Lp[SPLITS * NN];                     // split-K partial rowsums
__device__ __align__(16) float2 g_elx[NN];
__device__ __align__(16) float2 g_erx[NN];
__device__ float  g_ul[IND];
__device__ float  g_ur[IND];
__device__ float  g_cb[2];

// ---------------- helpers ----------------
__device__ __forceinline__ uint32_t smem_u32(const void* p) {
    return (uint32_t)__cvta_generic_to_shared(p);
}
__device__ __forceinline__ void cp16(void* dst, const void* src) {
    asm volatile("cp.async.cg.shared.global [%0], [%1], 16;" ::
                 "r"(smem_u32(dst)), "l"(src) : "memory");
}
__device__ __forceinline__ void cp_commit() {
    asm volatile("cp.async.commit_group;" ::: "memory");
}
__device__ __forceinline__ void cp_wait0() {
    asm volatile("cp.async.wait_group 0;" ::: "memory");
}
__device__ __forceinline__ void cp_wait1() {
    asm volatile("cp.async.wait_group 1;" ::: "memory");
}
__device__ __forceinline__ float ex2f(float x) {
    float y; asm("ex2.approx.ftz.f32 %0, %1;" : "=f"(y) : "f"(x)); return y;
}
__device__ __forceinline__ uint32_t pack2h(__half a, __half b) {
    return (uint32_t)__half_as_ushort(a) | ((uint32_t)__half_as_ushort(b) << 16);
}
__device__ __forceinline__ void ldmA(uint32_t* r, const void* p) {
    uint32_t a = smem_u32(p);
    asm volatile("ldmatrix.sync.aligned.m8n8.x4.shared.b16 {%0,%1,%2,%3}, [%4];"
                 : "=r"(r[0]), "=r"(r[1]), "=r"(r[2]), "=r"(r[3]) : "r"(a));
}
__device__ __forceinline__ void ldmBT(uint32_t* r, const void* p) {
    uint32_t a = smem_u32(p);
    asm volatile("ldmatrix.sync.aligned.m8n8.x4.trans.shared.b16 {%0,%1,%2,%3}, [%4];"
                 : "=r"(r[0]), "=r"(r[1]), "=r"(r[2]), "=r"(r[3]) : "r"(a));
}
__device__ __forceinline__ void mma16816(float* c, const uint32_t* a,
                                         uint32_t b0, uint32_t b1) {
    asm volatile(
        "mma.sync.aligned.m16n8k16.row.col.f32.f16.f16.f32 "
        "{%0,%1,%2,%3},{%4,%5,%6,%7},{%8,%9},{%0,%1,%2,%3};"
        : "+f"(c[0]), "+f"(c[1]), "+f"(c[2]), "+f"(c[3])
        : "r"(a[0]), "r"(a[1]), "r"(a[2]), "r"(a[3]), "r"(b0), "r"(b1));
}

// ---------------- kernel 1: u_l = W @ a_l, u_r = W @ a_r ----------------
__global__ void __launch_bounds__(256) u_kernel(const float* __restrict__ W,
                                                const float* __restrict__ b,
                                                const float* __restrict__ a,
                                                const float* __restrict__ ab) {
    __shared__ float sa[2 * OUTD];
    const int tid = threadIdx.x;
    sa[tid]       = a[tid];
    sa[tid + 256] = a[tid + 256];
    __syncthreads();
    const int lane = tid & 31;
    const int k    = blockIdx.x * 8 + (tid >> 5);   // 0..511
    const float* wr = W + (size_t)k * OUTD + lane * 8;
    float4 v0 = *(const float4*)(wr);
    float4 v1 = *(const float4*)(wr + 4);
    const float* s0 = sa + lane * 8;
    const float* s1 = sa + OUTD + lane * 8;
    float ul = v0.x * s0[0] + v0.y * s0[1] + v0.z * s0[2] + v0.w * s0[3]
             + v1.x * s0[4] + v1.y * s0[5] + v1.z * s0[6] + v1.w * s0[7];
    float ur = v0.x * s1[0] + v0.y * s1[1] + v0.z * s1[2] + v0.w * s1[3]
             + v1.x * s1[4] + v1.y * s1[5] + v1.z * s1[6] + v1.w * s1[7];
    #pragma unroll
    for (int o = 16; o > 0; o >>= 1) {
        ul += __shfl_xor_sync(0xffffffffu, ul, o);
        ur += __shfl_xor_sync(0xffffffffu, ur, o);
    }
    if (lane == 0) { g_ul[k] = ul; g_ur[k] = ur; }
    if (blockIdx.x == 0 && tid == 0) {
        float bl = 0.f, br = 0.f;
        for (int n = 0; n < OUTD; ++n) {
            bl += b[n] * sa[n];
            br += b[n] * sa[OUTD + n];
        }
        g_cb[0] = bl + ab[0];   // a_bias folded into el
        g_cb[1] = br;
    }
}

// ---------------- kernel 2: per-node factorized exps of el/er ----------------
__global__ void __launch_bounds__(256) eler_kernel(const float* __restrict__ X) {
    __shared__ float sul[IND], sur[IND];
    const int tid = threadIdx.x;
    sul[tid]       = g_ul[tid];
    sul[tid + 256] = g_ul[tid + 256];
    sur[tid]       = g_ur[tid];
    sur[tid + 256] = g_ur[tid + 256];
    __syncthreads();
    const int lane = tid & 31;
    const int w    = tid >> 5;
    const int i    = blockIdx.x * 8 + w;
    const float* xr = X + (size_t)i * IND;
    float dl = 0.f, dr = 0.f;
    #pragma unroll
    for (int q = 0; q < 4; ++q) {
        int c = q * 128 + lane * 4;
        float4 v = *(const float4*)(xr + c);
        dl += v.x * sul[c] + v.y * sul[c + 1] + v.z * sul[c + 2] + v.w * sul[c + 3];
        dr += v.x * sur[c] + v.y * sur[c + 1] + v.z * sur[c + 2] + v.w * sur[c + 3];
    }
    #pragma unroll
    for (int o = 16; o > 0; o >>= 1) {
        dl += __shfl_xor_sync(0xffffffffu, dl, o);
        dr += __shfl_xor_sync(0xffffffffu, dr, o);
    }
    if (lane == 0) {
        float el = dl + g_cb[0];
        float er = dr + g_cb[1];
        float2 ev, fv;
        ev.x = ex2f(el * LOG2E - 3.0f);
        ev.y = ex2f(el * (0.2f * LOG2E) - 3.0f);
        fv.x = ex2f(er * LOG2E - 3.0f);
        fv.y = ex2f(er * (0.2f * LOG2E) - 3.0f);
        g_elx[i] = ev;
        g_erx[i] = fv;
    }
}

// ---------------- kernel 3: h16 = fp16(X @ W + b), row-major ----------------
__global__ void __launch_bounds__(256) gemm1_kernel(const float* __restrict__ X,
                                                    const float* __restrict__ W,
                                                    const float* __restrict__ b) {
    __shared__ __half sX[128 * 72];
    __shared__ __half sW[64 * 136];
    const int tid  = threadIdx.x;
    const int lane = tid & 31;
    const int wid  = tid >> 5;
    const int mblk = blockIdx.x * 128;
    const int nblk = blockIdx.y * 128;
    const int wm   = (wid >> 1) * 32;
    const int wn   = (wid & 1) * 64;

    float acc[2][8][4];
    #pragma unroll
    for (int i = 0; i < 2; ++i)
        #pragma unroll
        for (int j = 0; j < 8; ++j)
            #pragma unroll
            for (int k = 0; k < 4; ++k) acc[i][j][k] = 0.f;

    for (int k0 = 0; k0 < IND; k0 += 64) {
        __syncthreads();
        #pragma unroll
        for (int pass = 0; pass < 8; ++pass) {
            int row = pass * 16 + (tid >> 4);
            int col = (tid & 15) * 4;
            float4 v = *(const float4*)(X + (size_t)(mblk + row) * IND + k0 + col);
            *(__half2*)&sX[row * 72 + col]     = __floats2half2_rn(v.x, v.y);
            *(__half2*)&sX[row * 72 + col + 2] = __floats2half2_rn(v.z, v.w);
        }
        #pragma unroll
        for (int pass = 0; pass < 8; ++pass) {
            int row = pass * 8 + (tid >> 5);
            int col = (tid & 31) * 4;
            float4 v = *(const float4*)(W + (size_t)(k0 + row) * OUTD + nblk + col);
            *(__half2*)&sW[row * 136 + col]     = __floats2half2_rn(v.x, v.y);
            *(__half2*)&sW[row * 136 + col + 2] = __floats2half2_rn(v.z, v.w);
        }
        __syncthreads();
        #pragma unroll
        for (int kk = 0; kk < 4; ++kk) {
            int kb = kk * 16;
            uint32_t A[2][4];
            #pragma unroll
            for (int mf = 0; mf < 2; ++mf)
                ldmA(A[mf], &sX[(wm + mf * 16 + (lane & 15)) * 72 + kb + (lane >> 4) * 8]);
            #pragma unroll
            for (int nf = 0; nf < 4; ++nf) {
                uint32_t B[4];
                ldmBT(B, &sW[(kb + (lane & 15)) * 136 + wn + nf * 16 + (lane >> 4) * 8]);
                #pragma unroll
                for (int mf = 0; mf < 2; ++mf) {
                    mma16816(acc[mf][2 * nf],     A[mf], B[0], B[1]);
                    mma16816(acc[mf][2 * nf + 1], A[mf], B[2], B[3]);
                }
            }
        }
    }
    #pragma unroll
    for (int mf = 0; mf < 2; ++mf) {
        int grow = mblk + wm + mf * 16 + (lane >> 2);
        #pragma unroll
        for (int nf = 0; nf < 8; ++nf) {
            int gcol = nblk + wn + nf * 8 + (lane & 3) * 2;
            float b0 = b[gcol], b1 = b[gcol + 1];
            *(__half2*)&g_h16[(size_t)grow * OUTD + gcol] =
                __floats2half2_rn(acc[mf][nf][0] + b0, acc[mf][nf][1] + b1);
            *(__half2*)&g_h16[(size_t)(grow + 8) * OUTD + gcol] =
                __floats2half2_rn(acc[mf][nf][2] + b0, acc[mf][nf][3] + b1);
        }
    }
}

// ---------------- kernel 4: fused masked-softmax attention ----------------
// one __syncthreads per tile; 3-stage H cp.async pipeline; swizzled smem
__global__ void __launch_bounds__(256, 2) gat_fused_kernel(const int* __restrict__ adj) {
    extern __shared__ __align__(1024) char smem[];

    const int tid  = threadIdx.x;
    const int lane = tid & 31;
    const int wid  = tid >> 5;
    const int s    = blockIdx.x & 1;
    const int rb   = blockIdx.x >> 1;
    const int i0   = rb * BM;
    const int J0   = s * JRANGE;

    const int r  = tid >> 2;           // 0..63 (P row)
    const int cq = tid & 3;            // col quarter
    const int cg = cq << 4;            // 0,16,32,48
    const int* arow = adj + (size_t)(i0 + r) * NN + J0 + cg;

    const float2 ev = g_elx[i0 + r];   // per-thread row factor (constant over tiles)

    // prologue: stage H tiles 0 and 1 (separate commit groups)
    #pragma unroll
    for (int tt = 0; tt < 2; ++tt) {
        #pragma unroll
        for (int p = 0; p < 8; ++p) {
            int idx = p * 256 + tid;
            int row = idx >> 5, cb = idx & 31;
            cp16(smem + SH_OFF + tt * SH_BUF + row * 512 + SWZ(row, cb),
                 g_h16 + (size_t)(J0 + tt * BK + row) * OUTD + cb * 8);
        }
        cp_commit();
    }

    int4 a_cur[4];
    #pragma unroll
    for (int q = 0; q < 4; ++q) a_cur[q] = __ldcs((const int4*)(arow + 4 * q));

    float acc[2][8][4];
    #pragma unroll
    for (int i = 0; i < 2; ++i)
        #pragma unroll
        for (int j = 0; j < 8; ++j)
            #pragma unroll
            for (int k = 0; k < 4; ++k) acc[i][j][k] = 0.f;
    float psum = 0.f;

    const int wm = (wid >> 2) * 32;
    const int wn = (wid & 3) * 64;

    for (int t = 0; t < NTILES; ++t) {
        const int jb = J0 + t * BK;

        // erx loads for this tile — issued before the cp-wait to hide L2 latency
        float4 u[8];
        #pragma unroll
        for (int q = 0; q < 4; ++q) {
            u[2 * q]     = *(const float4*)(g_erx + jb + cg + 4 * q);
            u[2 * q + 1] = *(const float4*)(g_erx + jb + cg + 4 * q + 2);
        }

        if (t < NTILES - 1) cp_wait1();   // H[t] ready; H[t+1] may be in flight
        else                cp_wait0();

        // P tile (64x64): p = adj ? (e1*f1 > 2^-6 ? e1*f1 : e2*f2) : 0
        {
            uint32_t pk[8];
            #pragma unroll
            for (int q = 0; q < 4; ++q) {
                const int4 av = a_cur[q];
                const int   mv[4] = {av.x, av.y, av.z, av.w};
                const float e1[4] = {u[2*q].x, u[2*q].z, u[2*q+1].x, u[2*q+1].z};
                const float e2[4] = {u[2*q].y, u[2*q].w, u[2*q+1].y, u[2*q+1].w};
                __half ph[4];
                #pragma unroll
                for (int e = 0; e < 4; ++e) {
                    float p1 = ev.x * e1[e];
                    float p2 = ev.y * e2[e];
                    float p  = (p1 > THRESH) ? p1 : p2;
                    p = (mv[e] > 0) ? p : 0.f;
                    psum += p;
                    ph[e] = __float2half_rn(p);
                }
                pk[2 * q]     = pack2h(ph[0], ph[1]);
                pk[2 * q + 1] = pack2h(ph[2], ph[3]);
            }
            char* pb = smem + SP_OFF + (t & 1) * SP_BUF + r * 128;
            *(uint4*)(pb + SWZ(r, 2 * cq))     = make_uint4(pk[0], pk[1], pk[2], pk[3]);
            *(uint4*)(pb + SWZ(r, 2 * cq + 1)) = make_uint4(pk[4], pk[5], pk[6], pk[7]);
        }

        // prefetch adj for tile t+1 (returns during MMA)
        if (t + 1 < NTILES) {
            const int* an = arow + (t + 1) * BK;
            #pragma unroll
            for (int q = 0; q < 4; ++q) a_cur[q] = __ldcs((const int4*)(an + 4 * q));
        }

        __syncthreads();   // P[t] visible; MMA[t-1] done by all -> H[(t+2)%3] free

        // issue H cp for tile t+2
        if (t + 2 < NTILES) {
            const int nb = (t + 2) % 3;
            const int jn = J0 + (t + 2) * BK;
            #pragma unroll
            for (int p = 0; p < 8; ++p) {
                int idx = p * 256 + tid;
                int row = idx >> 5, cb = idx & 31;
                cp16(smem + SH_OFF + nb * SH_BUF + row * 512 + SWZ(row, cb),
                     g_h16 + (size_t)(jn + row) * OUTD + cb * 8);
            }
            cp_commit();
        }

        // MMA: acc += P(64x64) @ H(64x256)
        const char* sPb = smem + SP_OFF + (t & 1) * SP_BUF;
        const char* sHb = smem + SH_OFF + (t % 3) * SH_BUF;
        #pragma unroll
        for (int kk = 0; kk < 4; ++kk) {
            uint32_t A[2][4];
            #pragma unroll
            for (int mf = 0; mf < 2; ++mf) {
                int prow = wm + mf * 16 + (lane & 15);
                ldmA(A[mf], sPb + prow * 128 + SWZ(prow, kk * 2 + (lane >> 4)));
            }
            #pragma unroll
            for (int nf = 0; nf < 4; ++nf) {
                int krow = kk * 16 + (lane & 15);
                uint32_t B[4];
                ldmBT(B, sHb + krow * 512 + SWZ(krow, (wn >> 3) + nf * 2 + (lane >> 4)));
                #pragma unroll
                for (int mf = 0; mf < 2; ++mf) {
                    mma16816(acc[mf][2 * nf],     A[mf], B[0], B[1]);
                    mma16816(acc[mf][2 * nf + 1], A[mf], B[2], B[3]);
                }
            }
        }
    }

    // rowsum reduce: threads 4r..4r+3 are consecutive lanes
    psum += __shfl_xor_sync(0xffffffffu, psum, 1);
    psum += __shfl_xor_sync(0xffffffffu, psum, 2);
    if ((tid & 3) == 0) g_Lp[s * NN + i0 + r] = psum;

    // write partial numerators
    #pragma unroll
    for (int mf = 0; mf < 2; ++mf) {
        int row0 = wm + mf * 16 + (lane >> 2);
        float* d0 = g_part + ((size_t)s * NN + i0 + row0) * OUTD;
        float* d1 = g_part + ((size_t)s * NN + i0 + row0 + 8) * OUTD;
        #pragma unroll
        for (int nf = 0; nf < 8; ++nf) {
            int col = wn + nf * 8 + (lane & 3) * 2;
            *(float2*)(d0 + col) = make_float2(acc[mf][nf][0], acc[mf][nf][1]);
            *(float2*)(d1 + col) = make_float2(acc[mf][nf][2], acc[mf][nf][3]);
        }
    }
}

// ---------------- kernel 5: combine split-K partials ----------------
__global__ void __launch_bounds__(256) combine_kernel(float* __restrict__ out) {
    const int gid = blockIdx.x * 256 + threadIdx.x;
    const int row = gid >> 6;
    const int c   = (gid & 63) * 4;
    const float4 x0 = *(const float4*)(g_part + (size_t)row * OUTD + c);
    const float4 x1 = *(const float4*)(g_part + (size_t)NN * OUTD + (size_t)row * OUTD + c);
    const float inv = 1.0f / (g_Lp[row] + g_Lp[NN + row]);
    float4 o;
    o.x = (x0.x + x1.x) * inv;
    o.y = (x0.y + x1.y) * inv;
    o.z = (x0.z + x1.z) * inv;
    o.w = (x0.w + x1.w) * inv;
    *(float4*)(out + (size_t)row * OUTD + c) = o;
}

// ---------------- launch ----------------
extern "C" void kernel_launch(void* const* d_in, const int* in_sizes, int n_in,
                              void* d_out, int out_size) {
    const int*   adj = (const int*)d_in[0];
    const float* X   = (const float*)d_in[1];
    const float* W   = (const float*)d_in[2];
    const float* b   = (const float*)d_in[3];
    const float* a   = (const float*)d_in[4];
    const float* ab  = (const float*)d_in[5];
    float* out = (float*)d_out;

    cudaFuncSetAttribute(gat_fused_kernel,
                         cudaFuncAttributeMaxDynamicSharedMemorySize, SMEM_FUSED);

    u_kernel<<<64, 256>>>(W, b, a, ab);
    eler_kernel<<<NN / 8, 256>>>(X);
    gemm1_kernel<<<dim3(NN / 128, OUTD / 128), 256>>>(X, W, b);
    gat_fused_kernel<<<(NN / BM) * SPLITS, 256, SMEM_FUSED>>>(adj);
    combine_kernel<<<(NN * OUTD / 4) / 256, 256>>>(out);
}